// round 7
// baseline (speedup 1.0000x reference)
#include <cuda_runtime.h>

// metaCLF R6: same algorithm as R5 (V=2 packed-f32x2, 2-kernel split),
// occupancy attack: 64-thread blocks so the register file quantizes finer.
//   f_kernel: launch_bounds(64,5) -> 320 thr/SM (10 warps) vs 256 (8)
//   y_kernel: launch_bounds(64,6) -> 384 thr/SM (12 warps)
// plus f register trim (store e[3][3] per pair, recompute kron partials
// inside the G1 loop).

typedef unsigned long long u64;

#define HWD   (96*96*96)   // 884736
#define NQUAD (HWD/4)      // 221184 quads (4 voxels) per batch
#define NB    2
#define TPB   64

// scratch for y = G3^T x  (static __device__ array: allowed)
__device__ float y_buf[(long long)NB * 64 * HWD];

__device__ __forceinline__ u64 bc2(float w) {
    u64 r; asm("mov.b64 %0, {%1, %2};" : "=l"(r) : "f"(w), "f"(w)); return r;
}
__device__ __forceinline__ u64 fma2(u64 a, u64 b, u64 c) {
    u64 d; asm("fma.rn.f32x2 %0, %1, %2, %3;" : "=l"(d) : "l"(a), "l"(b), "l"(c)); return d;
}
__device__ __forceinline__ u64 mul2(u64 a, u64 b) {
    u64 d; asm("mul.rn.f32x2 %0, %1, %2;" : "=l"(d) : "l"(a), "l"(b)); return d;
}
__device__ __forceinline__ u64 add2(u64 a, u64 b) {
    u64 d; asm("add.rn.f32x2 %0, %1, %2;" : "=l"(d) : "l"(a), "l"(b)); return d;
}
__device__ __forceinline__ u64 relu2(u64 a) {
    float lo, hi;
    asm("mov.b64 {%0, %1}, %2;" : "=f"(lo), "=f"(hi) : "l"(a));
    lo = fmaxf(lo, 0.0f); hi = fmaxf(hi, 0.0f);
    u64 r; asm("mov.b64 %0, {%1, %2};" : "=l"(r) : "f"(lo), "f"(hi));
    return r;
}
__device__ __forceinline__ void lds2(const u64* p, u64& a, u64& b) {
    unsigned long long sp = __cvta_generic_to_shared(p);
    asm("ld.shared.v2.b64 {%0, %1}, [%2];" : "=l"(a), "=l"(b) : "l"(sp));
}

// ===================== Kernel Y: y = G3^T x =====================
__global__ void __launch_bounds__(TPB, 6)
y_kernel(const float* __restrict__ x, const float* __restrict__ G3)
{
    __shared__ __align__(16) u64 sG3t[2048];   // [k][c] packed {w,w}
    for (int i = threadIdx.x; i < 2048; i += TPB) {
        int k = i >> 5, c = i & 31;
        sG3t[i] = bc2(G3[c * 64 + k]);
    }
    __syncthreads();

    const int q = blockIdx.x * TPB + threadIdx.x;    // quad index (exact grid)
    const int b = q / NQUAD;
    const long long v = (long long)(q - b * NQUAD) * 4;

    const float* xb = x + (long long)b * 32 * HWD + v;
    u64 xA[32], xB[32];
#pragma unroll
    for (int c = 0; c < 32; ++c) {
        ulonglong2 p = *(const ulonglong2*)(xb + (long long)c * HWD);
        xA[c] = p.x; xB[c] = p.y;
    }

    float* yb = y_buf + (long long)b * 64 * HWD + v;
#pragma unroll 4
    for (int k = 0; k < 64; ++k) {
        const u64* row = sG3t + k * 32;
        u64 sA0 = 0, sA1 = 0, sB0 = 0, sB1 = 0;
#pragma unroll
        for (int c = 0; c < 32; c += 2) {
            u64 w0, w1; lds2(row + c, w0, w1);
            sA0 = fma2(w0, xA[c],     sA0);
            sB0 = fma2(w0, xB[c],     sB0);
            sA1 = fma2(w1, xA[c + 1], sA1);
            sB1 = fma2(w1, xB[c + 1], sB1);
        }
        ulonglong2 o; o.x = add2(sA0, sA1); o.y = add2(sB0, sB1);
        *(ulonglong2*)(yb + (long long)k * HWD) = o;
    }
}

// ============ Kernel F: encode->G1->G2 + fused dot with y ============
// smem layout (u64 units): W1 @0 [32], W2T @32 [64], G1T @96 [27*32], G2 @960 [64*32]
#define FOFF_W1   0
#define FOFF_W2T  32
#define FOFF_G1T  96
#define FOFF_G2   960
#define FSW_TOT   3008

__global__ void __launch_bounds__(TPB, 5)
f_kernel(const float* __restrict__ d_all,
         const float* __restrict__ W1, const float* __restrict__ W2,
         const float* __restrict__ G1, const float* __restrict__ G2,
         float* __restrict__ out)
{
    __shared__ __align__(16) u64 sw[FSW_TOT];
    {
        const int t = threadIdx.x;
        for (int i = t; i < 32; i += TPB) sw[FOFF_W1 + i] = bc2(W1[i]);
        for (int i = t; i < 64; i += TPB) {
            int j = i >> 2, o = i & 3;
            sw[FOFF_W2T + i] = (o < 3) ? bc2(W2[o * 16 + j]) : 0ull;
        }
        for (int i = t; i < 864; i += TPB) {
            int e = i >> 5, c = i & 31;                 // G1T [e][c]
            sw[FOFF_G1T + i] = bc2(G1[c * 27 + e]);
        }
        for (int i = t; i < 2048; i += TPB) sw[FOFF_G2 + i] = bc2(G2[i]);
    }
    __syncthreads();
    const u64* sW1  = sw + FOFF_W1;
    const u64* sW2t = sw + FOFF_W2T;
    const u64* sG1t = sw + FOFF_G1T;
    const u64* sG2  = sw + FOFF_G2;

    const int q = blockIdx.x * TPB + threadIdx.x;
    const int b = q / NQUAD;
    const long long v = (long long)(q - b * NQUAD) * 4;

    // ---- encode both pairs (weights shared across pairs) ----
    const float* db = d_all + (long long)b * 6 * HWD + v;
    u64 eA[3][3], eB[3][3];
#pragma unroll
    for (int a = 0; a < 3; ++a) {
        ulonglong2 r0 = *(const ulonglong2*)(db + (long long)(2 * a + 0) * HWD);
        ulonglong2 r1 = *(const ulonglong2*)(db + (long long)(2 * a + 1) * HWD);
        const u64 dA0 = r0.x, dB0 = r0.y, dA1 = r1.x, dB1 = r1.y;
        u64 aA0 = 0, aA1 = 0, aA2 = 0, aB0 = 0, aB1 = 0, aB2 = 0;
#pragma unroll
        for (int j = 0; j < 16; ++j) {
            u64 w10, w11; lds2(sW1 + 2 * j, w10, w11);
            u64 tA = relu2(fma2(w10, dA0, mul2(w11, dA1)));
            u64 tB = relu2(fma2(w10, dB0, mul2(w11, dB1)));
            u64 w20, w21; lds2(sW2t + 4 * j, w20, w21);
            const u64 w22 = sW2t[4 * j + 2];
            aA0 = fma2(w20, tA, aA0);  aB0 = fma2(w20, tB, aB0);
            aA1 = fma2(w21, tA, aA1);  aB1 = fma2(w21, tB, aB1);
            aA2 = fma2(w22, tA, aA2);  aB2 = fma2(w22, tB, aB2);
        }
        eA[a][0] = aA0; eA[a][1] = aA1; eA[a][2] = aA2;
        eB[a][0] = aB0; eB[a][1] = aB1; eB[a][2] = aB2;
    }

    // ---- G1, e-major; kron partials recomputed in-loop (reg trim) ----
    u64 hA[32], hB[32];
#pragma unroll
    for (int c = 0; c < 32; ++c) { hA[c] = 0ull; hB[c] = 0ull; }
#pragma unroll 1
    for (int ij = 0; ij < 9; ++ij) {
        const u64 pA = mul2(eA[0][ij / 3], eA[1][ij % 3]);
        const u64 pB = mul2(eB[0][ij / 3], eB[1][ij % 3]);
#pragma unroll
        for (int kk = 0; kk < 3; ++kk) {
            const u64 encA = mul2(pA, eA[2][kk]);
            const u64 encB = mul2(pB, eB[2][kk]);
            const u64* row = sG1t + (ij * 3 + kk) * 32;
#pragma unroll
            for (int c = 0; c < 32; c += 2) {
                u64 w0, w1; lds2(row + c, w0, w1);
                hA[c]     = fma2(w0, encA, hA[c]);
                hB[c]     = fma2(w0, encB, hB[c]);
                hA[c + 1] = fma2(w1, encA, hA[c + 1]);
                hB[c + 1] = fma2(w1, encB, hB[c + 1]);
            }
        }
    }
#pragma unroll
    for (int c = 0; c < 32; ++c) { hA[c] = relu2(hA[c]); hB[c] = relu2(hB[c]); }

    // ---- k-loop: out += relu(G2[k]·h) * y_k ----
    const float* yb = y_buf + (long long)b * 64 * HWD + v;
    u64 accA = 0ull, accB = 0ull;
#pragma unroll 4
    for (int k = 0; k < 64; ++k) {
        const u64* row = sG2 + k * 32;
        u64 sA0 = 0, sA1 = 0, sB0 = 0, sB1 = 0;
#pragma unroll
        for (int c = 0; c < 32; c += 2) {
            u64 w0, w1; lds2(row + c, w0, w1);
            sA0 = fma2(w0, hA[c],     sA0);
            sB0 = fma2(w0, hB[c],     sB0);
            sA1 = fma2(w1, hA[c + 1], sA1);
            sB1 = fma2(w1, hB[c + 1], sB1);
        }
        const u64 hkA = relu2(add2(sA0, sA1));
        const u64 hkB = relu2(add2(sB0, sB1));
        ulonglong2 y2 = *(const ulonglong2*)(yb + (long long)k * HWD);
        accA = fma2(hkA, y2.x, accA);
        accB = fma2(hkB, y2.y, accB);
    }

    ulonglong2 o; o.x = accA; o.y = accB;
    *(ulonglong2*)(out + (long long)b * HWD + v) = o;
}

extern "C" void kernel_launch(void* const* d_in, const int* in_sizes, int n_in,
                              void* d_out, int out_size)
{
    const float* x    = (const float*)d_in[0];
    const float* dall = (const float*)d_in[1];
    const float* W1   = (const float*)d_in[2];
    const float* W2   = (const float*)d_in[3];
    const float* G1   = (const float*)d_in[4];
    const float* G2   = (const float*)d_in[5];
    const float* G3   = (const float*)d_in[6];
    float* out = (float*)d_out;

    const int total_threads = NB * NQUAD;      // 442368 = 6912 * 64
    dim3 grid(total_threads / TPB);
    y_kernel<<<grid, TPB>>>(x, G3);
    f_kernel<<<grid, TPB>>>(dall, W1, W2, G1, G2, out);
}

// round 8
// speedup vs baseline: 1.1097x; 1.1097x over previous
#include <cuda_runtime.h>

// metaCLF R7: R5 structure (V=2 packed-f32x2, 2-kernel split, 128-thr
// blocks, fully-unrolled G1) + R6's register trim (e[3][3] storage,
// pij recomputed) WITHOUT the unroll-1 pessimization, capped at
// launch_bounds(128,3) for 12 warps/SM.

typedef unsigned long long u64;

#define HWD   (96*96*96)   // 884736
#define NQUAD (HWD/4)      // 221184 quads (4 voxels) per batch
#define NB    2
#define TPB   128

// scratch for y = G3^T x  (static __device__ array: allowed)
__device__ float y_buf[(long long)NB * 64 * HWD];

__device__ __forceinline__ u64 bc2(float w) {
    u64 r; asm("mov.b64 %0, {%1, %2};" : "=l"(r) : "f"(w), "f"(w)); return r;
}
__device__ __forceinline__ u64 fma2(u64 a, u64 b, u64 c) {
    u64 d; asm("fma.rn.f32x2 %0, %1, %2, %3;" : "=l"(d) : "l"(a), "l"(b), "l"(c)); return d;
}
__device__ __forceinline__ u64 mul2(u64 a, u64 b) {
    u64 d; asm("mul.rn.f32x2 %0, %1, %2;" : "=l"(d) : "l"(a), "l"(b)); return d;
}
__device__ __forceinline__ u64 add2(u64 a, u64 b) {
    u64 d; asm("add.rn.f32x2 %0, %1, %2;" : "=l"(d) : "l"(a), "l"(b)); return d;
}
__device__ __forceinline__ u64 relu2(u64 a) {
    float lo, hi;
    asm("mov.b64 {%0, %1}, %2;" : "=f"(lo), "=f"(hi) : "l"(a));
    lo = fmaxf(lo, 0.0f); hi = fmaxf(hi, 0.0f);
    u64 r; asm("mov.b64 %0, {%1, %2};" : "=l"(r) : "f"(lo), "f"(hi));
    return r;
}
__device__ __forceinline__ void lds2(const u64* p, u64& a, u64& b) {
    unsigned long long sp = __cvta_generic_to_shared(p);
    asm("ld.shared.v2.b64 {%0, %1}, [%2];" : "=l"(a), "=l"(b) : "l"(sp));
}

// ===================== Kernel Y: y = G3^T x =====================
__global__ void __launch_bounds__(TPB, 3)
y_kernel(const float* __restrict__ x, const float* __restrict__ G3)
{
    __shared__ __align__(16) u64 sG3t[2048];   // [k][c] packed {w,w}
    for (int i = threadIdx.x; i < 2048; i += TPB) {
        int k = i >> 5, c = i & 31;
        sG3t[i] = bc2(G3[c * 64 + k]);
    }
    __syncthreads();

    const int q = blockIdx.x * TPB + threadIdx.x;    // quad index (exact grid)
    const int b = q / NQUAD;
    const long long v = (long long)(q - b * NQUAD) * 4;

    const float* xb = x + (long long)b * 32 * HWD + v;
    u64 xA[32], xB[32];
#pragma unroll
    for (int c = 0; c < 32; ++c) {
        ulonglong2 p = *(const ulonglong2*)(xb + (long long)c * HWD);
        xA[c] = p.x; xB[c] = p.y;
    }

    float* yb = y_buf + (long long)b * 64 * HWD + v;
#pragma unroll 4
    for (int k = 0; k < 64; ++k) {
        const u64* row = sG3t + k * 32;
        u64 sA0 = 0, sA1 = 0, sB0 = 0, sB1 = 0;
#pragma unroll
        for (int c = 0; c < 32; c += 2) {
            u64 w0, w1; lds2(row + c, w0, w1);
            sA0 = fma2(w0, xA[c],     sA0);
            sB0 = fma2(w0, xB[c],     sB0);
            sA1 = fma2(w1, xA[c + 1], sA1);
            sB1 = fma2(w1, xB[c + 1], sB1);
        }
        ulonglong2 o; o.x = add2(sA0, sA1); o.y = add2(sB0, sB1);
        *(ulonglong2*)(yb + (long long)k * HWD) = o;
    }
}

// ============ Kernel F: encode->G1->G2 + fused dot with y ============
// smem layout (u64 units): W1 @0 [32], W2T @32 [64], G1T @96 [27*32], G2 @960 [64*32]
#define FOFF_W1   0
#define FOFF_W2T  32
#define FOFF_G1T  96
#define FOFF_G2   960
#define FSW_TOT   3008

__global__ void __launch_bounds__(TPB, 3)
f_kernel(const float* __restrict__ d_all,
         const float* __restrict__ W1, const float* __restrict__ W2,
         const float* __restrict__ G1, const float* __restrict__ G2,
         float* __restrict__ out)
{
    __shared__ __align__(16) u64 sw[FSW_TOT];
    {
        const int t = threadIdx.x;
        for (int i = t; i < 32; i += TPB) sw[FOFF_W1 + i] = bc2(W1[i]);
        for (int i = t; i < 64; i += TPB) {
            int j = i >> 2, o = i & 3;
            sw[FOFF_W2T + i] = (o < 3) ? bc2(W2[o * 16 + j]) : 0ull;
        }
        for (int i = t; i < 864; i += TPB) {
            int e = i >> 5, c = i & 31;                 // G1T [e][c]
            sw[FOFF_G1T + i] = bc2(G1[c * 27 + e]);
        }
        for (int i = t; i < 2048; i += TPB) sw[FOFF_G2 + i] = bc2(G2[i]);
    }
    __syncthreads();
    const u64* sW1  = sw + FOFF_W1;
    const u64* sW2t = sw + FOFF_W2T;
    const u64* sG1t = sw + FOFF_G1T;
    const u64* sG2  = sw + FOFF_G2;

    const int q = blockIdx.x * TPB + threadIdx.x;
    const int b = q / NQUAD;
    const long long v = (long long)(q - b * NQUAD) * 4;

    // ---- encode both pairs (weights shared across pairs) ----
    const float* db = d_all + (long long)b * 6 * HWD + v;
    u64 eA[3][3], eB[3][3];
#pragma unroll
    for (int a = 0; a < 3; ++a) {
        ulonglong2 r0 = *(const ulonglong2*)(db + (long long)(2 * a + 0) * HWD);
        ulonglong2 r1 = *(const ulonglong2*)(db + (long long)(2 * a + 1) * HWD);
        const u64 dA0 = r0.x, dB0 = r0.y, dA1 = r1.x, dB1 = r1.y;
        u64 aA0 = 0, aA1 = 0, aA2 = 0, aB0 = 0, aB1 = 0, aB2 = 0;
#pragma unroll
        for (int j = 0; j < 16; ++j) {
            u64 w10, w11; lds2(sW1 + 2 * j, w10, w11);
            u64 tA = relu2(fma2(w10, dA0, mul2(w11, dA1)));
            u64 tB = relu2(fma2(w10, dB0, mul2(w11, dB1)));
            u64 w20, w21; lds2(sW2t + 4 * j, w20, w21);
            const u64 w22 = sW2t[4 * j + 2];
            aA0 = fma2(w20, tA, aA0);  aB0 = fma2(w20, tB, aB0);
            aA1 = fma2(w21, tA, aA1);  aB1 = fma2(w21, tB, aB1);
            aA2 = fma2(w22, tA, aA2);  aB2 = fma2(w22, tB, aB2);
        }
        eA[a][0] = aA0; eA[a][1] = aA1; eA[a][2] = aA2;
        eB[a][0] = aB0; eB[a][1] = aB1; eB[a][2] = aB2;
    }

    // ---- G1, e-major; kron partials recomputed (regs), fully unrolled ----
    u64 hA[32], hB[32];
#pragma unroll
    for (int c = 0; c < 32; ++c) { hA[c] = 0ull; hB[c] = 0ull; }
#pragma unroll 3
    for (int ij = 0; ij < 9; ++ij) {
        const u64 pA = mul2(eA[0][ij / 3], eA[1][ij % 3]);
        const u64 pB = mul2(eB[0][ij / 3], eB[1][ij % 3]);
#pragma unroll
        for (int kk = 0; kk < 3; ++kk) {
            const u64 encA = mul2(pA, eA[2][kk]);
            const u64 encB = mul2(pB, eB[2][kk]);
            const u64* row = sG1t + (ij * 3 + kk) * 32;
#pragma unroll
            for (int c = 0; c < 32; c += 2) {
                u64 w0, w1; lds2(row + c, w0, w1);
                hA[c]     = fma2(w0, encA, hA[c]);
                hB[c]     = fma2(w0, encB, hB[c]);
                hA[c + 1] = fma2(w1, encA, hA[c + 1]);
                hB[c + 1] = fma2(w1, encB, hB[c + 1]);
            }
        }
    }
#pragma unroll
    for (int c = 0; c < 32; ++c) { hA[c] = relu2(hA[c]); hB[c] = relu2(hB[c]); }

    // ---- k-loop: out += relu(G2[k]·h) * y_k ----
    const float* yb = y_buf + (long long)b * 64 * HWD + v;
    u64 accA = 0ull, accB = 0ull;
#pragma unroll 4
    for (int k = 0; k < 64; ++k) {
        const u64* row = sG2 + k * 32;
        // early y load so gmem latency overlaps the dot product
        ulonglong2 y2 = *(const ulonglong2*)(yb + (long long)k * HWD);
        u64 sA0 = 0, sA1 = 0, sB0 = 0, sB1 = 0;
#pragma unroll
        for (int c = 0; c < 32; c += 2) {
            u64 w0, w1; lds2(row + c, w0, w1);
            sA0 = fma2(w0, hA[c],     sA0);
            sB0 = fma2(w0, hB[c],     sB0);
            sA1 = fma2(w1, hA[c + 1], sA1);
            sB1 = fma2(w1, hB[c + 1], sB1);
        }
        const u64 hkA = relu2(add2(sA0, sA1));
        const u64 hkB = relu2(add2(sB0, sB1));
        accA = fma2(hkA, y2.x, accA);
        accB = fma2(hkB, y2.y, accB);
    }

    ulonglong2 o; o.x = accA; o.y = accB;
    *(ulonglong2*)(out + (long long)b * HWD + v) = o;
}

extern "C" void kernel_launch(void* const* d_in, const int* in_sizes, int n_in,
                              void* d_out, int out_size)
{
    const float* x    = (const float*)d_in[0];
    const float* dall = (const float*)d_in[1];
    const float* W1   = (const float*)d_in[2];
    const float* W2   = (const float*)d_in[3];
    const float* G1   = (const float*)d_in[4];
    const float* G2   = (const float*)d_in[5];
    const float* G3   = (const float*)d_in[6];
    float* out = (float*)d_out;

    const int total_threads = NB * NQUAD;      // 442368 = 3456 * 128
    dim3 grid(total_threads / TPB);
    y_kernel<<<grid, TPB>>>(x, G3);
    f_kernel<<<grid, TPB>>>(dall, W1, W2, G1, G2, out);
}